// round 3
// baseline (speedup 1.0000x reference)
#include <cuda_runtime.h>
#include <float.h>
#include <math.h>

#define BATCH 8
#define CH    64
#define NPT   4096
#define OUTC  64
#define KNN   20
#define CK    58          // channels 6..63 used for knn
#define SKIP  6
#define NEG   0.2f

typedef unsigned long long ull;

// ---------------- f32x2 packed math helpers (Blackwell) ---------------------
__device__ __forceinline__ ull ffma2(ull a, ull b, ull c) {
    ull d; asm("fma.rn.f32x2 %0, %1, %2, %3;" : "=l"(d) : "l"(a), "l"(b), "l"(c)); return d;
}
__device__ __forceinline__ ull add2(ull a, ull b) {
    ull d; asm("add.rn.f32x2 %0, %1, %2;" : "=l"(d) : "l"(a), "l"(b)); return d;
}
__device__ __forceinline__ ull pack2(float lo, float hi) {
    ull r; asm("mov.b64 %0, {%1, %2};" : "=l"(r) : "f"(lo), "f"(hi)); return r;
}
__device__ __forceinline__ void unpack2(ull v, float &lo, float &hi) {
    asm("mov.b64 {%0, %1}, %2;" : "=f"(lo), "=f"(hi) : "l"(v));
}

// ---------------- device scratch (static globals: allocation-free) ----------
__device__ float  g_sq  [BATCH*NPT];
__device__ int    g_idx [BATCH*NPT*KNN];
__device__ float  g_u   [BATCH*NPT*OUTC];   // [b][n][o]
__device__ float  g_v   [BATCH*NPT*OUTC];   // [b][n][o]
__device__ float  g_umax[BATCH*NPT*OUTC];   // [b][n][o]
__device__ float  g_umin[BATCH*NPT*OUTC];
__device__ double g_S1  [OUTC];
__device__ double g_S2  [OUTC];
__device__ float  g_ab  [2*OUTC];           // a, b' per channel

// ---------------- init: zero stat accumulators ------------------------------
__global__ void k_init() {
    int o = threadIdx.x;
    g_S1[o] = 0.0; g_S2[o] = 0.0;
}

// ---------------- squared norms over channels 6..63 -------------------------
__global__ void k_sq(const float* __restrict__ x) {
    int b = blockIdx.y;
    int n = blockIdx.x * 256 + threadIdx.x;
    const float* xb = x + (size_t)b * CH * NPT;
    float s = 0.f;
    #pragma unroll
    for (int c = SKIP; c < CH; c++) {
        float v = xb[c * NPT + n];
        s = fmaf(v, v, s);
    }
    g_sq[b * NPT + n] = s;
}

// ---------------- fused KNN: tiled inner-product GEMM + warp top-20 ---------
#define TI 64
#define TJ 256
#define CAP 32

// smem words: xjs[CK][TJ] | xis[CK][TI] | sqj[TJ] | sqi[TI]
//           | listd[TI][KNN] | listi[TI][KNN] | cd[TI][CAP] | cj[TI][CAP] | cnt[TI]
#define KNN_SMEM_WORDS (CK*TJ + CK*TI + TJ + TI + TI*KNN*2 + TI*CAP*2 + TI)
#define KNN_SMEM_BYTES (KNN_SMEM_WORDS * 4)

__global__ __launch_bounds__(256, 1) void k_knn(const float* __restrict__ x) {
    int b  = blockIdx.y;
    int i0 = blockIdx.x * TI;
    const float* xb = x + (size_t)b * CH * NPT + (size_t)SKIP * NPT; // [CK][NPT]

    extern __shared__ float sm[];
    float* xjs   = sm;                    // [CK][TJ]
    float* xis   = xjs + CK * TJ;         // [CK][TI]
    float* sqj   = xis + CK * TI;         // [TJ]
    float* sqi   = sqj + TJ;              // [TI]
    float* listd = sqi + TI;              // [TI][KNN]
    int*   listi = (int*)(listd + TI * KNN);
    float* cd    = (float*)(listi + TI * KNN);   // [TI][CAP]
    int*   cj    = (int*)(cd + TI * CAP);
    int*   cnt   = cj + TI * CAP;         // [TI]

    int tid  = threadIdx.x;
    int warp = tid >> 5, lane = tid & 31;
    int r0 = warp * 8;               // warp owns rows r0..r0+7
    int cA = lane * 4;               // cols cA..cA+3
    int cB = 128 + lane * 4;         // cols cB..cB+3

    for (int l = tid; l < TI * KNN; l += 256) { listd[l] = -FLT_MAX; listi[l] = 0x7FFFFFFF; }
    if (tid < TI) { cnt[tid] = 0; sqi[tid] = g_sq[b * NPT + i0 + tid]; }
    for (int l = tid; l < CK * TI; l += 256) {
        int c = l / TI, r = l % TI;
        xis[c * TI + r] = xb[(size_t)c * NPT + i0 + r];
    }
    __syncthreads();

    for (int jt = 0; jt < NPT; jt += TJ) {
        for (int l = tid; l < CK * TJ; l += 256) {
            int c = l >> 8, j = l & 255;
            xjs[c * TJ + j] = xb[(size_t)c * NPT + jt + j];
        }
        if (tid < TJ) sqj[tid] = g_sq[b * NPT + jt + tid];
        __syncthreads();

        // ---- 8x8 register-tile GEMM in packed f32x2 (rows a, col pairs dp)
        ull acc[8][4];
        #pragma unroll
        for (int a = 0; a < 8; a++)
            #pragma unroll
            for (int d = 0; d < 4; d++) acc[a][d] = 0ull;

        #pragma unroll 2
        for (int c = 0; c < CK; c++) {
            longlong2 xjA = *(const longlong2*)&xjs[c * TJ + cA];
            longlong2 xjB = *(const longlong2*)&xjs[c * TJ + cB];
            float4 xi0 = *(const float4*)&xis[c * TI + r0];
            float4 xi1 = *(const float4*)&xis[c * TI + r0 + 4];
            ull xjp[4] = { (ull)xjA.x, (ull)xjA.y, (ull)xjB.x, (ull)xjB.y };
            float xiA[8] = {xi0.x, xi0.y, xi0.z, xi0.w, xi1.x, xi1.y, xi1.z, xi1.w};
            #pragma unroll
            for (int a = 0; a < 8; a++) {
                ull xip = pack2(xiA[a], xiA[a]);
                #pragma unroll
                for (int d = 0; d < 4; d++)
                    acc[a][d] = ffma2(xip, xjp[d], acc[a][d]);
            }
        }

        // ---- epilogue: pd = 2*inner - sqi - sqj (packed)
        {
            float4 sj0 = *(const float4*)&sqj[cA];
            float4 sj1 = *(const float4*)&sqj[cB];
            ull nsj[4] = { pack2(-sj0.x, -sj0.y), pack2(-sj0.z, -sj0.w),
                           pack2(-sj1.x, -sj1.y), pack2(-sj1.z, -sj1.w) };
            const ull TWO2 = pack2(2.f, 2.f);
            #pragma unroll
            for (int a = 0; a < 8; a++) {
                float si = sqi[r0 + a];
                ull nsi = pack2(-si, -si);
                #pragma unroll
                for (int d = 0; d < 4; d++)
                    acc[a][d] = ffma2(acc[a][d], TWO2, add2(nsi, nsj[d]));
            }
        }

        // ---- warp-scoped top-20 selection (rows private to this warp)
        unsigned long long pend = ~0ull;
        for (;;) {
            bool ovf = false;
            #pragma unroll
            for (int a = 0; a < 8; a++) {
                if (((pend >> (a * 8)) & 0xFFull) == 0) continue;
                int r = r0 + a;
                float thr = listd[r * KNN + KNN - 1];
                int  thrj = listi[r * KNN + KNN - 1];
                #pragma unroll
                for (int dp = 0; dp < 4; dp++) {
                    int e = a * 8 + dp * 2;
                    if (((pend >> e) & 3ull) == 0) continue;
                    float lo, hi; unpack2(acc[a][dp], lo, hi);
                    int jlo = jt + (dp < 2 ? cA + dp * 2 : cB + (dp - 2) * 2);
                    if ((pend >> e) & 1ull) {
                        bool pass = (lo > thr) || (lo == thr && jlo < thrj);
                        if (!pass) pend &= ~(1ull << e);
                        else {
                            int pos = atomicAdd(&cnt[r], 1);
                            if (pos < CAP) { cd[r * CAP + pos] = lo; cj[r * CAP + pos] = jlo; pend &= ~(1ull << e); }
                            else ovf = true;
                        }
                    }
                    if ((pend >> (e + 1)) & 1ull) {
                        int jh = jlo + 1;
                        bool pass = (hi > thr) || (hi == thr && jh < thrj);
                        if (!pass) pend &= ~(1ull << (e + 1));
                        else {
                            int pos = atomicAdd(&cnt[r], 1);
                            if (pos < CAP) { cd[r * CAP + pos] = hi; cj[r * CAP + pos] = jh; pend &= ~(1ull << (e + 1)); }
                            else ovf = true;
                        }
                    }
                }
            }
            __syncwarp();
            if (lane < 8) {
                int r = r0 + lane;
                int m = min(cnt[r], CAP);
                for (int e = 0; e < m; e++) {
                    float pdv = cd[r * CAP + e];
                    int   j   = cj[r * CAP + e];
                    float td = listd[r * KNN + KNN - 1];
                    int   tj = listi[r * KNN + KNN - 1];
                    if ((pdv > td) || (pdv == td && j < tj)) {
                        int p = KNN - 1;
                        while (p > 0) {
                            float qd = listd[r * KNN + p - 1];
                            int   qj = listi[r * KNN + p - 1];
                            if ((pdv > qd) || (pdv == qd && j < qj)) {
                                listd[r * KNN + p] = qd;
                                listi[r * KNN + p] = qj;
                                p--;
                            } else break;
                        }
                        listd[r * KNN + p] = pdv;
                        listi[r * KNN + p] = j;
                    }
                }
                cnt[r] = 0;
            }
            bool anyovf = __any_sync(0xFFFFFFFFu, ovf);
            __syncwarp();
            if (!anyovf) break;
        }
        __syncthreads();   // all warps done with xjs before next tile reload
    }

    if (tid < TI) {
        int i = i0 + tid;
        #pragma unroll
        for (int k = 0; k < KNN; k++)
            g_idx[((size_t)b * NPT + i) * KNN + k] = listi[tid * KNN + k];
    }
}

// ---------------- projections u = W1 x, v = (W2 - W1) x ---------------------
__global__ __launch_bounds__(256) void k_proj(const float* __restrict__ x,
                                              const float* __restrict__ W) {
    int b = blockIdx.y;
    int n0 = blockIdx.x * 64;
    __shared__ float xs[64][64];
    __shared__ float w1t[64][64];   // [c][o]
    __shared__ float wvt[64][64];
    int tid = threadIdx.x;
    for (int l = tid; l < 64 * 64; l += 256) {
        int o = l >> 6, c = l & 63;
        float a = W[o * 128 + c];
        float bb = W[o * 128 + 64 + c];
        w1t[c][o] = a;
        wvt[c][o] = bb - a;
    }
    for (int l = tid; l < 64 * 64; l += 256) {
        int c = l >> 6, n = l & 63;
        xs[c][n] = x[((size_t)b * CH + c) * NPT + n0 + n];
    }
    __syncthreads();
    int o = tid & 63, ng = tid >> 6;
    for (int pass = 0; pass < 4; pass++) {
        int nl = pass * 16 + ng * 4;
        ull u0 = 0, u1 = 0, v0 = 0, v1 = 0;
        #pragma unroll
        for (int c = 0; c < 64; c++) {
            longlong2 xv = *(const longlong2*)&xs[c][nl];
            float w1 = w1t[c][o], wv = wvt[c][o];
            ull w1p = pack2(w1, w1), wvp = pack2(wv, wv);
            u0 = ffma2(w1p, (ull)xv.x, u0);
            u1 = ffma2(w1p, (ull)xv.y, u1);
            v0 = ffma2(wvp, (ull)xv.x, v0);
            v1 = ffma2(wvp, (ull)xv.y, v1);
        }
        size_t p = ((size_t)b * NPT + n0 + nl) * OUTC + o;
        float a0, a1;
        unpack2(u0, a0, a1); g_u[p] = a0; g_u[p + OUTC] = a1;
        unpack2(u1, a0, a1); g_u[p + 2 * OUTC] = a0; g_u[p + 3 * OUTC] = a1;
        unpack2(v0, a0, a1); g_v[p] = a0; g_v[p + OUTC] = a1;
        unpack2(v1, a0, a1); g_v[p + 2 * OUTC] = a0; g_v[p + 3 * OUTC] = a1;
    }
}

// ---------------- gather neighbors: umax/umin + fp64 BN stats ---------------
__global__ __launch_bounds__(256) void k_gather() {
    int b = blockIdx.y;
    int base = blockIdx.x * 128;
    int g = threadIdx.x >> 6;   // 0..3
    int o = threadIdx.x & 63;
    const float* ub = g_u + (size_t)b * NPT * OUTC;
    double d1 = 0.0, d2 = 0.0;
    for (int it = 0; it < 32; it++) {
        int i = base + g + (it << 2);
        const int* ip = &g_idx[((size_t)b * NPT + i) * KNN];
        float s1 = 0.f, s2 = 0.f, mx = -FLT_MAX, mn = FLT_MAX;
        #pragma unroll
        for (int k = 0; k < KNN; k++) {
            int j = __ldg(&ip[k]);
            float val = ub[(size_t)j * OUTC + o];
            s1 += val;
            s2 = fmaf(val, val, s2);
            mx = fmaxf(mx, val);
            mn = fminf(mn, val);
        }
        size_t p = ((size_t)b * NPT + i) * OUTC + o;
        float vv = g_v[p];
        g_umax[p] = mx;
        g_umin[p] = mn;
        d1 += (double)s1 + (double)KNN * (double)vv;
        d2 += (double)s2 + 2.0 * (double)vv * (double)s1 + (double)KNN * (double)vv * (double)vv;
    }
    __shared__ double sm1[4][64], sm2[4][64];
    sm1[g][o] = d1;
    sm2[g][o] = d2;
    __syncthreads();
    if (g == 0) {
        double a1 = sm1[0][o] + sm1[1][o] + sm1[2][o] + sm1[3][o];
        double a2 = sm2[0][o] + sm2[1][o] + sm2[2][o] + sm2[3][o];
        atomicAdd(&g_S1[o], a1);
        atomicAdd(&g_S2[o], a2);
    }
}

// ---------------- finalize BN affine ----------------------------------------
__global__ void k_final(const float* __restrict__ gamma, const float* __restrict__ beta) {
    int o = threadIdx.x;
    double M = (double)BATCH * NPT * KNN;
    double mean = g_S1[o] / M;
    double var  = g_S2[o] / M - mean * mean;
    double rs = 1.0 / sqrt(var + 1e-5);
    double a  = (double)gamma[o] * rs;
    double bb = (double)beta[o] - mean * a;
    g_ab[o] = (float)a;
    g_ab[64 + o] = (float)bb;
}

// ---------------- output: affine + LeakyReLU + max-over-k, transposed write -
__global__ void k_out(float* __restrict__ out) {
    int b = blockIdx.z;
    int n0 = blockIdx.x * 32;
    int o0 = blockIdx.y * 32;
    __shared__ float thi[32][33], tlo[32][33];
    int tx = threadIdx.x, ty = threadIdx.y;
    size_t p = ((size_t)b * NPT + n0 + ty) * OUTC + o0 + tx;
    float v = g_v[p];
    thi[ty][tx] = g_umax[p] + v;
    tlo[ty][tx] = g_umin[p] + v;
    __syncthreads();
    float a  = g_ab[o0 + ty];
    float bb = g_ab[64 + o0 + ty];
    float y = (a >= 0.f) ? thi[tx][ty] : tlo[tx][ty];
    float z = fmaf(a, y, bb);
    out[((size_t)b * OUTC + o0 + ty) * NPT + n0 + tx] = (z >= 0.f) ? z : NEG * z;
}

// ---------------- launcher ---------------------------------------------------
extern "C" void kernel_launch(void* const* d_in, const int* in_sizes, int n_in,
                              void* d_out, int out_size) {
    const float* x     = (const float*)d_in[0];
    const float* W     = (const float*)d_in[1];
    const float* gamma = (const float*)d_in[2];
    const float* beta  = (const float*)d_in[3];
    float* out = (float*)d_out;

    cudaFuncSetAttribute(k_knn, cudaFuncAttributeMaxDynamicSharedMemorySize, KNN_SMEM_BYTES);

    k_init  <<<1, 64>>>();
    k_sq    <<<dim3(NPT / 256, BATCH), 256>>>(x);
    k_knn   <<<dim3(NPT / TI, BATCH), 256, KNN_SMEM_BYTES>>>(x);
    k_proj  <<<dim3(NPT / 64, BATCH), 256>>>(x, W);
    k_gather<<<dim3(NPT / 128, BATCH), 256>>>();
    k_final <<<1, 64>>>(gamma, beta);
    k_out   <<<dim3(NPT / 32, OUTC / 32, BATCH), dim3(32, 32)>>>(out);
}

// round 4
// speedup vs baseline: 2.6251x; 2.6251x over previous
#include <cuda_runtime.h>
#include <float.h>
#include <math.h>

#define BATCH 8
#define CH    64
#define NPT   4096
#define OUTC  64
#define KNN   20
#define CK    58          // channels 6..63 used for knn
#define SKIP  6
#define NEG   0.2f

typedef unsigned long long ull;

// ---------------- f32x2 packed math helpers (Blackwell) ---------------------
__device__ __forceinline__ ull ffma2(ull a, ull b, ull c) {
    ull d; asm("fma.rn.f32x2 %0, %1, %2, %3;" : "=l"(d) : "l"(a), "l"(b), "l"(c)); return d;
}
__device__ __forceinline__ ull add2(ull a, ull b) {
    ull d; asm("add.rn.f32x2 %0, %1, %2;" : "=l"(d) : "l"(a), "l"(b)); return d;
}
__device__ __forceinline__ ull pack2(float lo, float hi) {
    ull r; asm("mov.b64 %0, {%1, %2};" : "=l"(r) : "f"(lo), "f"(hi)); return r;
}
__device__ __forceinline__ void unpack2(ull v, float &lo, float &hi) {
    asm("mov.b64 {%0, %1}, %2;" : "=f"(lo), "=f"(hi) : "l"(v));
}

// ---------------- device scratch (static globals: allocation-free) ----------
__device__ float  g_sq  [BATCH*NPT];
__device__ int    g_idx [BATCH*NPT*KNN];
__device__ float  g_u   [BATCH*NPT*OUTC];   // [b][n][o]
__device__ float  g_v   [BATCH*NPT*OUTC];   // [b][n][o]
__device__ float  g_umax[BATCH*NPT*OUTC];   // [b][n][o]
__device__ float  g_umin[BATCH*NPT*OUTC];
__device__ double g_S1  [OUTC];
__device__ double g_S2  [OUTC];
__device__ float  g_ab  [2*OUTC];           // a, b' per channel

// ---------------- init: zero stat accumulators ------------------------------
__global__ void k_init() {
    int o = threadIdx.x;
    g_S1[o] = 0.0; g_S2[o] = 0.0;
}

// ---------------- squared norms over channels 6..63 -------------------------
__global__ void k_sq(const float* __restrict__ x) {
    int b = blockIdx.y;
    int n = blockIdx.x * 256 + threadIdx.x;
    const float* xb = x + (size_t)b * CH * NPT;
    float s = 0.f;
    #pragma unroll
    for (int c = SKIP; c < CH; c++) {
        float v = xb[c * NPT + n];
        s = fmaf(v, v, s);
    }
    g_sq[b * NPT + n] = s;
}

// ---------------- fused KNN: tiled inner-product GEMM + warp top-20 ---------
#define TI 64
#define TJ 256
#define CAP 32

// smem words: xjs[CK][TJ] | xis[CK][TI] | sqj[TJ] | sqi[TI]
//           | listd[TI][KNN] | listi[TI][KNN] | cd[TI][CAP] | cj[TI][CAP] | cnt[TI]
#define KNN_SMEM_WORDS (CK*TJ + CK*TI + TJ + TI + TI*KNN*2 + TI*CAP*2 + TI)
#define KNN_SMEM_BYTES (KNN_SMEM_WORDS * 4)

__global__ __launch_bounds__(256, 2) void k_knn(const float* __restrict__ x) {
    int b  = blockIdx.y;
    int i0 = blockIdx.x * TI;
    const float* xb = x + (size_t)b * CH * NPT + (size_t)SKIP * NPT; // [CK][NPT]

    extern __shared__ float sm[];
    float* xjs   = sm;                    // [CK][TJ]
    float* xis   = xjs + CK * TJ;         // [CK][TI]
    float* sqj   = xis + CK * TI;         // [TJ]
    float* sqi   = sqj + TJ;              // [TI]
    float* listd = sqi + TI;              // [TI][KNN]
    int*   listi = (int*)(listd + TI * KNN);
    float* cd    = (float*)(listi + TI * KNN);   // [TI][CAP]
    int*   cj    = (int*)(cd + TI * CAP);
    int*   cnt   = cj + TI * CAP;         // [TI]

    int tid  = threadIdx.x;
    int warp = tid >> 5, lane = tid & 31;
    int r0 = warp * 8;               // warp owns rows r0..r0+7
    int cA = lane * 4;               // cols cA..cA+3
    int cB = 128 + lane * 4;         // cols cB..cB+3

    for (int l = tid; l < TI * KNN; l += 256) { listd[l] = -FLT_MAX; listi[l] = 0x7FFFFFFF; }
    if (tid < TI) { cnt[tid] = 0; sqi[tid] = g_sq[b * NPT + i0 + tid]; }
    // vectorized xi tile load: CK*TI/4 = 928 float4s
    for (int l = tid; l < CK * (TI / 4); l += 256) {
        int c = l >> 4, rq = l & 15;
        *(float4*)&xis[c * TI + rq * 4] = *(const float4*)&xb[(size_t)c * NPT + i0 + rq * 4];
    }
    __syncthreads();

    for (int jt = 0; jt < NPT; jt += TJ) {
        // vectorized xj tile load: CK*TJ/4 = 3712 float4s
        for (int l = tid; l < CK * (TJ / 4); l += 256) {
            int c = l >> 6, jq = l & 63;
            *(float4*)&xjs[c * TJ + jq * 4] = *(const float4*)&xb[(size_t)c * NPT + jt + jq * 4];
        }
        if (tid < TJ) sqj[tid] = g_sq[b * NPT + jt + tid];
        __syncthreads();

        // ---- 8x8 register-tile GEMM in packed f32x2 (rows a, col pairs dp)
        ull acc[8][4];
        #pragma unroll
        for (int a = 0; a < 8; a++)
            #pragma unroll
            for (int d = 0; d < 4; d++) acc[a][d] = 0ull;

        #pragma unroll 2
        for (int c = 0; c < CK; c++) {
            longlong2 xjA = *(const longlong2*)&xjs[c * TJ + cA];
            longlong2 xjB = *(const longlong2*)&xjs[c * TJ + cB];
            float4 xi0 = *(const float4*)&xis[c * TI + r0];
            float4 xi1 = *(const float4*)&xis[c * TI + r0 + 4];
            ull xjp[4] = { (ull)xjA.x, (ull)xjA.y, (ull)xjB.x, (ull)xjB.y };
            float xiA[8] = {xi0.x, xi0.y, xi0.z, xi0.w, xi1.x, xi1.y, xi1.z, xi1.w};
            #pragma unroll
            for (int a = 0; a < 8; a++) {
                ull xip = pack2(xiA[a], xiA[a]);
                #pragma unroll
                for (int d = 0; d < 4; d++)
                    acc[a][d] = ffma2(xip, xjp[d], acc[a][d]);
            }
        }

        // ---- epilogue: pd = 2*inner - sqi - sqj (packed)
        {
            float4 sj0 = *(const float4*)&sqj[cA];
            float4 sj1 = *(const float4*)&sqj[cB];
            ull nsj[4] = { pack2(-sj0.x, -sj0.y), pack2(-sj0.z, -sj0.w),
                           pack2(-sj1.x, -sj1.y), pack2(-sj1.z, -sj1.w) };
            const ull TWO2 = pack2(2.f, 2.f);
            #pragma unroll
            for (int a = 0; a < 8; a++) {
                float si = sqi[r0 + a];
                ull nsi = pack2(-si, -si);
                #pragma unroll
                for (int d = 0; d < 4; d++)
                    acc[a][d] = ffma2(acc[a][d], TWO2, add2(nsi, nsj[d]));
            }
        }

        // ---- row-max pre-filter: clear rows that cannot contribute ---------
        unsigned long long pend = 0ull;
        #pragma unroll
        for (int a = 0; a < 8; a++) {
            float thr = listd[(r0 + a) * KNN + KNN - 1];
            float mx = -FLT_MAX;
            #pragma unroll
            for (int d = 0; d < 4; d++) {
                float lo, hi; unpack2(acc[a][d], lo, hi);
                mx = fmaxf(mx, fmaxf(lo, hi));
            }
            if (mx >= thr) pend |= (0xFFull << (a * 8));
        }

        // ---- warp-scoped top-20 selection (rows private to this warp)
        for (;;) {
            bool ovf = false;
            #pragma unroll
            for (int a = 0; a < 8; a++) {
                if (((pend >> (a * 8)) & 0xFFull) == 0) continue;
                int r = r0 + a;
                float thr = listd[r * KNN + KNN - 1];
                int  thrj = listi[r * KNN + KNN - 1];
                #pragma unroll
                for (int dp = 0; dp < 4; dp++) {
                    int e = a * 8 + dp * 2;
                    if (((pend >> e) & 3ull) == 0) continue;
                    float lo, hi; unpack2(acc[a][dp], lo, hi);
                    int jlo = jt + (dp < 2 ? cA + dp * 2 : cB + (dp - 2) * 2);
                    if ((pend >> e) & 1ull) {
                        bool pass = (lo > thr) || (lo == thr && jlo < thrj);
                        if (!pass) pend &= ~(1ull << e);
                        else {
                            int pos = atomicAdd(&cnt[r], 1);
                            if (pos < CAP) { cd[r * CAP + pos] = lo; cj[r * CAP + pos] = jlo; pend &= ~(1ull << e); }
                            else ovf = true;
                        }
                    }
                    if ((pend >> (e + 1)) & 1ull) {
                        int jh = jlo + 1;
                        bool pass = (hi > thr) || (hi == thr && jh < thrj);
                        if (!pass) pend &= ~(1ull << (e + 1));
                        else {
                            int pos = atomicAdd(&cnt[r], 1);
                            if (pos < CAP) { cd[r * CAP + pos] = hi; cj[r * CAP + pos] = jh; pend &= ~(1ull << (e + 1)); }
                            else ovf = true;
                        }
                    }
                }
            }
            __syncwarp();
            if (lane < 8) {
                int r = r0 + lane;
                int m = min(cnt[r], CAP);
                for (int e = 0; e < m; e++) {
                    float pdv = cd[r * CAP + e];
                    int   j   = cj[r * CAP + e];
                    float td = listd[r * KNN + KNN - 1];
                    int   tj = listi[r * KNN + KNN - 1];
                    if ((pdv > td) || (pdv == td && j < tj)) {
                        int p = KNN - 1;
                        while (p > 0) {
                            float qd = listd[r * KNN + p - 1];
                            int   qj = listi[r * KNN + p - 1];
                            if ((pdv > qd) || (pdv == qd && j < qj)) {
                                listd[r * KNN + p] = qd;
                                listi[r * KNN + p] = qj;
                                p--;
                            } else break;
                        }
                        listd[r * KNN + p] = pdv;
                        listi[r * KNN + p] = j;
                    }
                }
                cnt[r] = 0;
            }
            bool anyovf = __any_sync(0xFFFFFFFFu, ovf);
            __syncwarp();
            if (!anyovf) break;
        }
        __syncthreads();   // all warps done with xjs before next tile reload
    }

    if (tid < TI) {
        int i = i0 + tid;
        #pragma unroll
        for (int k = 0; k < KNN; k++)
            g_idx[((size_t)b * NPT + i) * KNN + k] = listi[tid * KNN + k];
    }
}

// ---------------- projections u = W1 x, v = (W2 - W1) x ---------------------
__global__ __launch_bounds__(256) void k_proj(const float* __restrict__ x,
                                              const float* __restrict__ W) {
    int b = blockIdx.y;
    int n0 = blockIdx.x * 128;
    __shared__ float xs[64][128];
    __shared__ float w1t[64][64];   // [c][o]
    __shared__ float wvt[64][64];
    int tid = threadIdx.x;
    for (int l = tid; l < 64 * 64; l += 256) {
        int o = l >> 6, c = l & 63;
        float a = W[o * 128 + c];
        float bb = W[o * 128 + 64 + c];
        w1t[c][o] = a;
        wvt[c][o] = bb - a;
    }
    for (int l = tid; l < 64 * 32; l += 256) {
        int c = l >> 5, nq = l & 31;
        *(float4*)&xs[c][nq * 4] = *(const float4*)&x[((size_t)b * CH + c) * NPT + n0 + nq * 4];
    }
    __syncthreads();
    int o = tid & 63, ng = tid >> 6;
    for (int pass = 0; pass < 8; pass++) {
        int nl = pass * 16 + ng * 4;
        ull u0 = 0, u1 = 0, v0 = 0, v1 = 0;
        #pragma unroll
        for (int c = 0; c < 64; c++) {
            longlong2 xv = *(const longlong2*)&xs[c][nl];
            float w1 = w1t[c][o], wv = wvt[c][o];
            ull w1p = pack2(w1, w1), wvp = pack2(wv, wv);
            u0 = ffma2(w1p, (ull)xv.x, u0);
            u1 = ffma2(w1p, (ull)xv.y, u1);
            v0 = ffma2(wvp, (ull)xv.x, v0);
            v1 = ffma2(wvp, (ull)xv.y, v1);
        }
        size_t p = ((size_t)b * NPT + n0 + nl) * OUTC + o;
        float a0, a1;
        unpack2(u0, a0, a1); g_u[p] = a0; g_u[p + OUTC] = a1;
        unpack2(u1, a0, a1); g_u[p + 2 * OUTC] = a0; g_u[p + 3 * OUTC] = a1;
        unpack2(v0, a0, a1); g_v[p] = a0; g_v[p + OUTC] = a1;
        unpack2(v1, a0, a1); g_v[p + 2 * OUTC] = a0; g_v[p + 3 * OUTC] = a1;
    }
}

// ---------------- gather neighbors: umax/umin + fp64 BN stats ---------------
__global__ __launch_bounds__(256) void k_gather() {
    int b = blockIdx.y;
    int base = blockIdx.x * 128;
    int g = threadIdx.x >> 6;   // 0..3
    int o = threadIdx.x & 63;
    const float* ub = g_u + (size_t)b * NPT * OUTC;
    double d1 = 0.0, d2 = 0.0;
    for (int it = 0; it < 32; it++) {
        int i = base + g + (it << 2);
        const int* ip = &g_idx[((size_t)b * NPT + i) * KNN];
        float s1 = 0.f, s2 = 0.f, mx = -FLT_MAX, mn = FLT_MAX;
        #pragma unroll
        for (int k = 0; k < KNN; k++) {
            int j = __ldg(&ip[k]);
            float val = ub[(size_t)j * OUTC + o];
            s1 += val;
            s2 = fmaf(val, val, s2);
            mx = fmaxf(mx, val);
            mn = fminf(mn, val);
        }
        size_t p = ((size_t)b * NPT + i) * OUTC + o;
        float vv = g_v[p];
        g_umax[p] = mx;
        g_umin[p] = mn;
        d1 += (double)s1 + (double)KNN * (double)vv;
        d2 += (double)s2 + 2.0 * (double)vv * (double)s1 + (double)KNN * (double)vv * (double)vv;
    }
    __shared__ double sm1[4][64], sm2[4][64];
    sm1[g][o] = d1;
    sm2[g][o] = d2;
    __syncthreads();
    if (g == 0) {
        double a1 = sm1[0][o] + sm1[1][o] + sm1[2][o] + sm1[3][o];
        double a2 = sm2[0][o] + sm2[1][o] + sm2[2][o] + sm2[3][o];
        atomicAdd(&g_S1[o], a1);
        atomicAdd(&g_S2[o], a2);
    }
}

// ---------------- finalize BN affine ----------------------------------------
__global__ void k_final(const float* __restrict__ gamma, const float* __restrict__ beta) {
    int o = threadIdx.x;
    double M = (double)BATCH * NPT * KNN;
    double mean = g_S1[o] / M;
    double var  = g_S2[o] / M - mean * mean;
    double rs = 1.0 / sqrt(var + 1e-5);
    double a  = (double)gamma[o] * rs;
    double bb = (double)beta[o] - mean * a;
    g_ab[o] = (float)a;
    g_ab[64 + o] = (float)bb;
}

// ---------------- output: affine + LeakyReLU + max-over-k, transposed write -
__global__ void k_out(float* __restrict__ out) {
    int b = blockIdx.z;
    int n0 = blockIdx.x * 32;
    int o0 = blockIdx.y * 32;
    __shared__ float thi[32][33], tlo[32][33];
    int tx = threadIdx.x, ty = threadIdx.y;
    size_t p = ((size_t)b * NPT + n0 + ty) * OUTC + o0 + tx;
    float v = g_v[p];
    thi[ty][tx] = g_umax[p] + v;
    tlo[ty][tx] = g_umin[p] + v;
    __syncthreads();
    float a  = g_ab[o0 + ty];
    float bb = g_ab[64 + o0 + ty];
    float y = (a >= 0.f) ? thi[tx][ty] : tlo[tx][ty];
    float z = fmaf(a, y, bb);
    out[((size_t)b * OUTC + o0 + ty) * NPT + n0 + tx] = (z >= 0.f) ? z : NEG * z;
}

// ---------------- launcher ---------------------------------------------------
// NOTE: k_knn intentionally placed at launch index 3 (where ncu's capture
// window landed in previous rounds) so the next profile shows the hot kernel.
extern "C" void kernel_launch(void* const* d_in, const int* in_sizes, int n_in,
                              void* d_out, int out_size) {
    const float* x     = (const float*)d_in[0];
    const float* W     = (const float*)d_in[1];
    const float* gamma = (const float*)d_in[2];
    const float* beta  = (const float*)d_in[3];
    float* out = (float*)d_out;

    cudaFuncSetAttribute(k_knn, cudaFuncAttributeMaxDynamicSharedMemorySize, KNN_SMEM_BYTES);

    k_init  <<<1, 64>>>();
    k_sq    <<<dim3(NPT / 256, BATCH), 256>>>(x);
    k_proj  <<<dim3(NPT / 128, BATCH), 256>>>(x, W);
    k_knn   <<<dim3(NPT / TI, BATCH), 256, KNN_SMEM_BYTES>>>(x);
    k_gather<<<dim3(NPT / 128, BATCH), 256>>>();
    k_final <<<1, 64>>>(gamma, beta);
    k_out   <<<dim3(NPT / 32, OUTC / 32, BATCH), dim3(32, 32)>>>(out);
}